// round 12
// baseline (speedup 1.0000x reference)
#include <cuda_runtime.h>
#include <cuda_bf16.h>
#include <cstdint>

#define NTOT 65536
#define DDIM 512
#define KCL  64

#define BN 128              // d-columns per CTA tile
#define BK 32               // k rows per stage
#define DTILES 4            // DDIM / BN
#define NCHUNKS 128         // grid = 4*128 = 512 CTAs, ITERS = 16 uniform
#define NCTAS (DTILES * NCHUNKS)
#define ITERS 16
#define DEPTH 3             // smem ring depth

#define SF_B 144            // F smem row stride bytes (64 bf16 = 128 + 16 pad)
#define SH_B 272            // H smem row stride bytes (128 bf16 = 256 + 16 pad)

__device__ float        g_partial[KCL * DDIM];  // .bss zero; re-zeroed per call
__device__ float        g_h2sum;
__device__ unsigned int g_count;

__device__ __forceinline__ uint32_t smem_u32(const void* p) {
    return (uint32_t)__cvta_generic_to_shared(p);
}

__device__ __forceinline__ uint32_t pack_bf16(float lo, float hi) {
    uint32_t r;
    asm("cvt.rn.bf16x2.f32 %0, %1, %2;" : "=r"(r) : "f"(hi), "f"(lo));
    return r;
}

__device__ __forceinline__ void ldsm4t(uint32_t* r, uint32_t addr) {
    asm volatile(
        "ldmatrix.sync.aligned.m8n8.x4.trans.shared.b16 {%0,%1,%2,%3}, [%4];"
        : "=r"(r[0]), "=r"(r[1]), "=r"(r[2]), "=r"(r[3]) : "r"(addr));
}

__global__ __launch_bounds__(256, 2)
void k_fused(const float* __restrict__ H, const float* __restrict__ Fm,
             float* __restrict__ out) {
    __shared__ __align__(16) char Fs[DEPTH][BK * SF_B];   // 3 x 4608 B
    __shared__ __align__(16) char Hs[DEPTH][BK * SH_B];   // 3 x 8704 B
    __shared__ float        redbuf[8];
    __shared__ double       sb[8];
    __shared__ unsigned int s_ticket;

    const int tid  = threadIdx.x;
    const int lane = tid & 31;
    const int wid  = tid >> 5;
    const int d0   = blockIdx.x * BN;
    const int nb0  = blockIdx.y * (ITERS * BK);

    const int wm = (wid >> 2) * 32;     // 2 warp groups along m
    const int wn = (wid & 3) * 32;      // 4 warps along n (d)
    const int g  = lane >> 2;
    const int t  = lane & 3;

    // producer lane mapping (R9-proven)
    const int lk = lane >> 4;
    const int lq = lane & 15;

    // LDSM per-lane offsets (R9-proven)
    const uint32_t a_lane = (uint32_t)(((lane >> 4) & 1) * (8 * SF_B)
                                       + (lane & 7) * SF_B
                                       + ((lane >> 3) & 1) * 16);
    const uint32_t b_lane = (uint32_t)(((lane >> 3) & 1) * (8 * SH_B)
                                       + (lane & 7) * SH_B
                                       + ((lane >> 4) & 1) * 16);

    float acc[2][4][4];
#pragma unroll
    for (int a = 0; a < 2; a++)
#pragma unroll
        for (int b = 0; b < 4; b++)
#pragma unroll
            for (int cc = 0; cc < 4; cc++) acc[a][b][cc] = 0.f;

    float h2 = 0.f;

    float4 rhv[2][2][2];    // [reg slot][j][s] — H prefetch distance 2
    float4 rfv[2];          // F prefetch distance 1

    auto gloadH = [&](int it, int slot) {
        const int nb = nb0 + it * BK;
#pragma unroll
        for (int j = 0; j < 2; j++) {
            const int k = nb + 2 * (wid + 8 * j) + lk;
#pragma unroll
            for (int s = 0; s < 2; s++)
                rhv[slot][j][s] =
                    *(const float4*)&H[(size_t)k * DDIM + d0 + s * 64 + lq * 4];
        }
    };

    auto gloadF = [&](int it) {
        const int nb = nb0 + it * BK;
#pragma unroll
        for (int j = 0; j < 2; j++) {
            const int k = nb + 2 * (wid + 8 * j) + lk;
            rfv[j] = *(const float4*)&Fm[(size_t)k * KCL + lq * 4];
        }
    };

    auto sstore = [&](int stg, int slot) {
        char* fb = Fs[stg % DEPTH];
        char* hb = Hs[stg % DEPTH];
#pragma unroll
        for (int j = 0; j < 2; j++) {
            const int k = 2 * (wid + 8 * j) + lk;
            *(uint2*)(fb + k * SF_B + lq * 8) =
                make_uint2(pack_bf16(rfv[j].x, rfv[j].y),
                           pack_bf16(rfv[j].z, rfv[j].w));
#pragma unroll
            for (int s = 0; s < 2; s++) {
                float4 v = rhv[slot][j][s];
                *(uint2*)(hb + k * SH_B + s * 128 + lq * 8) =
                    make_uint2(pack_bf16(v.x, v.y), pack_bf16(v.z, v.w));
                h2 = fmaf(v.x, v.x, h2);
                h2 = fmaf(v.y, v.y, h2);
                h2 = fmaf(v.z, v.z, h2);
                h2 = fmaf(v.w, v.w, h2);
            }
        }
    };

    auto compute = [&](int stg) {
        const int buf = stg % DEPTH;
        const uint32_t aBase = smem_u32(Fs[buf]) + (uint32_t)(wm * 2) + a_lane;
        const uint32_t bBase = smem_u32(Hs[buf]) + (uint32_t)(wn * 2) + b_lane;
#pragma unroll
        for (int ks = 0; ks < 2; ks++) {          // two k16 steps per BK=32
            uint32_t a[2][4], b[2][4];
            ldsm4t(a[0], aBase + ks * (16 * SF_B));
            ldsm4t(a[1], aBase + ks * (16 * SF_B) + 32);
            ldsm4t(b[0], bBase + ks * (16 * SH_B));
            ldsm4t(b[1], bBase + ks * (16 * SH_B) + 32);
#pragma unroll
            for (int mi = 0; mi < 2; mi++)
#pragma unroll
                for (int ni = 0; ni < 4; ni++) {
                    const uint32_t b0 = b[ni >> 1][(ni & 1) * 2];
                    const uint32_t b1 = b[ni >> 1][(ni & 1) * 2 + 1];
                    asm volatile(
                        "mma.sync.aligned.m16n8k16.row.col.f32.bf16.bf16.f32 "
                        "{%0,%1,%2,%3}, {%4,%5,%6,%7}, {%8,%9}, {%0,%1,%2,%3};\n"
                        : "+f"(acc[mi][ni][0]), "+f"(acc[mi][ni][1]),
                          "+f"(acc[mi][ni][2]), "+f"(acc[mi][ni][3])
                        : "r"(a[mi][0]), "r"(a[mi][1]),
                          "r"(a[mi][2]), "r"(a[mi][3]),
                          "r"(b0), "r"(b1));
                }
        }
    };

    // ---- prologue: H(0)->slot0, H(1)->slot1, F(0); stage 0 to smem ----
    gloadH(0, 0);
    gloadF(0);
    gloadH(1, 1);
    sstore(0, 0);
    __syncthreads();

    // ---- main loop: H distance 2, F distance 1, one barrier per stage ----
#pragma unroll 1
    for (int it = 0; it < ITERS; ++it) {
        if (it + 2 < ITERS) gloadH(it + 2, it & 1);
        if (it + 1 < ITERS) gloadF(it + 1);
        compute(it);
        if (it + 1 < ITERS) sstore(it + 1, (it + 1) & 1);
        __syncthreads();
    }

    // ---- epilogue: packed float2 L2 atomics into partial G[m][d] ----
#pragma unroll
    for (int mi = 0; mi < 2; mi++)
#pragma unroll
        for (int ni = 0; ni < 4; ni++) {
            int m = wm + mi * 16 + g;
            int n = d0 + wn + ni * 8 + 2 * t;
            atomicAdd((float2*)&g_partial[m * DDIM + n],
                      make_float2(acc[mi][ni][0], acc[mi][ni][1]));
            atomicAdd((float2*)&g_partial[(m + 8) * DDIM + n],
                      make_float2(acc[mi][ni][2], acc[mi][ni][3]));
        }

    // ---- h2 block reduce, one atomic per CTA ----
#pragma unroll
    for (int o = 16; o > 0; o >>= 1) h2 += __shfl_xor_sync(0xffffffffu, h2, o);
    if (lane == 0) redbuf[wid] = h2;
    __syncthreads();
    if (tid == 0) {
        float s = 0.f;
#pragma unroll
        for (int w = 0; w < 8; w++) s += redbuf[w];
        atomicAdd(&g_h2sum, s);
    }

    // ---- last-CTA finalize: square-sum G, write scalar, reset state ----
    __threadfence();
    if (tid == 0) s_ticket = atomicAdd(&g_count, 1u);
    __syncthreads();
    if (s_ticket != NCTAS - 1) return;

    double s = 0.0;
    for (int i = tid; i < KCL * DDIM; i += 256) {
        float v = __ldcg(&g_partial[i]);
        s += (double)v * (double)v;
        g_partial[i] = 0.f;              // re-zero for next graph replay
    }
#pragma unroll
    for (int o = 16; o > 0; o >>= 1) s += __shfl_xor_sync(0xffffffffu, s, o);
    if (lane == 0) sb[wid] = s;
    __syncthreads();
    if (tid == 0) {
        double tot = 0.0;
#pragma unroll
        for (int w = 0; w < 8; w++) tot += sb[w];
        float h2tot = __ldcg(&g_h2sum);
        out[0] = (float)((double)h2tot - tot);
        g_h2sum = 0.f;
        g_count = 0u;
    }
}

extern "C" void kernel_launch(void* const* d_in, const int* in_sizes, int n_in,
                              void* d_out, int out_size) {
    const float* Hp;
    const float* Fp;
    if (in_sizes[0] == NTOT * DDIM) {
        Hp = (const float*)d_in[0];
        Fp = (const float*)d_in[1];
    } else {
        Hp = (const float*)d_in[1];
        Fp = (const float*)d_in[0];
    }

    dim3 grid(DTILES, NCHUNKS);
    k_fused<<<grid, 256>>>(Hp, Fp, (float*)d_out);
}

// round 13
// speedup vs baseline: 1.2912x; 1.2912x over previous
#include <cuda_runtime.h>
#include <cuda_bf16.h>
#include <cstdint>

#define NTOT 65536
#define DDIM 512
#define KCL  64

#define BN 128              // d-columns per CTA tile
#define BK 32               // k rows per stage
#define DTILES 4            // DDIM / BN
#define NCHUNKS 128         // grid = 4*128 = 512 CTAs (R1-proven sweet spot)
#define NCTAS (DTILES * NCHUNKS)
#define ITERS 16            // 2048 k-blocks / 128 chunks

#define SF_B 144            // F smem row stride bytes (64 bf16 = 128 + 16 pad)
#define SH_B 272            // H smem row stride bytes (128 bf16 = 256 + 16 pad)

__device__ float        g_partial[KCL * DDIM];  // .bss zero; re-zeroed per call
__device__ float        g_h2sum;
__device__ unsigned int g_count;

__device__ __forceinline__ uint32_t smem_u32(const void* p) {
    return (uint32_t)__cvta_generic_to_shared(p);
}

__device__ __forceinline__ uint32_t pack_bf16(float lo, float hi) {
    uint32_t r;
    asm("cvt.rn.bf16x2.f32 %0, %1, %2;" : "=r"(r) : "f"(hi), "f"(lo));
    return r;
}

__device__ __forceinline__ void ldsm4t(uint32_t* r, uint32_t addr) {
    asm volatile(
        "ldmatrix.sync.aligned.m8n8.x4.trans.shared.b16 {%0,%1,%2,%3}, [%4];"
        : "=r"(r[0]), "=r"(r[1]), "=r"(r[2]), "=r"(r[3]) : "r"(addr));
}

__global__ __launch_bounds__(256, 2)
void k_fused(const float* __restrict__ H, const float* __restrict__ Fm,
             float* __restrict__ out) {
    // smem tiles stay in gmem order: rows = k, padded strides for LDSM/STS
    __shared__ __align__(16) char Fs[2][BK * SF_B];   // 2 x 4608 B
    __shared__ __align__(16) char Hs[2][BK * SH_B];   // 2 x 8704 B
    __shared__ float        redbuf[8];
    __shared__ double       sb[8];
    __shared__ unsigned int s_ticket;

    const int tid  = threadIdx.x;
    const int lane = tid & 31;
    const int wid  = tid >> 5;
    const int d0   = blockIdx.x * BN;
    const int nb0  = blockIdx.y * (ITERS * BK);

    const int wm = (wid >> 2) * 32;     // 2 warp groups along m
    const int wn = (wid & 3) * 32;      // 4 warps along n (d)
    const int g  = lane >> 2;
    const int t  = lane & 3;

    // producer mapping: lanes 0-15 -> k even, 16-31 -> k odd
    const int lk = lane >> 4;           // k offset within pair
    const int lq = lane & 15;           // 16B quad index

    // LDSM per-lane offsets (bytes)
    const uint32_t a_lane = (uint32_t)(((lane >> 4) & 1) * (8 * SF_B)
                                       + (lane & 7) * SF_B
                                       + ((lane >> 3) & 1) * 16);
    const uint32_t b_lane = (uint32_t)(((lane >> 3) & 1) * (8 * SH_B)
                                       + (lane & 7) * SH_B
                                       + ((lane >> 4) & 1) * 16);

    float acc[2][4][4];
#pragma unroll
    for (int a = 0; a < 2; a++)
#pragma unroll
        for (int b = 0; b < 4; b++)
#pragma unroll
            for (int cc = 0; cc < 4; cc++) acc[a][b][cc] = 0.f;

    float h2 = 0.f;

    float4 rf[2], rh[2][2];

    auto gload = [&](int nb) {
#pragma unroll
        for (int j = 0; j < 2; j++) {
            const int k = nb + 2 * (wid + 8 * j) + lk;
            rf[j] = *(const float4*)&Fm[(size_t)k * KCL + lq * 4];
#pragma unroll
            for (int s = 0; s < 2; s++)
                rh[j][s] = *(const float4*)&H[(size_t)k * DDIM + d0 + s * 64 + lq * 4];
        }
    };

    auto sstore = [&](int buf) {
        char* fb = Fs[buf];
        char* hb = Hs[buf];
#pragma unroll
        for (int j = 0; j < 2; j++) {
            const int k = 2 * (wid + 8 * j) + lk;
            uint2 fv = make_uint2(pack_bf16(rf[j].x, rf[j].y),
                                  pack_bf16(rf[j].z, rf[j].w));
            *(uint2*)(fb + k * SF_B + lq * 8) = fv;
#pragma unroll
            for (int s = 0; s < 2; s++) {
                float4 h4 = rh[j][s];
                uint2 hv = make_uint2(pack_bf16(h4.x, h4.y),
                                      pack_bf16(h4.z, h4.w));
                *(uint2*)(hb + k * SH_B + s * 128 + lq * 8) = hv;
                h2 = fmaf(h4.x, h4.x, h2);
                h2 = fmaf(h4.y, h4.y, h2);
                h2 = fmaf(h4.z, h4.z, h2);
                h2 = fmaf(h4.w, h4.w, h2);
            }
        }
    };

    auto compute = [&](int buf) {
        const uint32_t aBase = smem_u32(Fs[buf]) + (uint32_t)(wm * 2) + a_lane;
        const uint32_t bBase = smem_u32(Hs[buf]) + (uint32_t)(wn * 2) + b_lane;
#pragma unroll
        for (int ks = 0; ks < 2; ks++) {          // two k16 steps per BK=32
            uint32_t a[2][4], b[2][4];
            ldsm4t(a[0], aBase + ks * (16 * SF_B));
            ldsm4t(a[1], aBase + ks * (16 * SF_B) + 32);      // m + 16
            ldsm4t(b[0], bBase + ks * (16 * SH_B));
            ldsm4t(b[1], bBase + ks * (16 * SH_B) + 32);      // n + 16
#pragma unroll
            for (int mi = 0; mi < 2; mi++)
#pragma unroll
                for (int ni = 0; ni < 4; ni++) {
                    const uint32_t b0 = b[ni >> 1][(ni & 1) * 2];
                    const uint32_t b1 = b[ni >> 1][(ni & 1) * 2 + 1];
                    asm volatile(
                        "mma.sync.aligned.m16n8k16.row.col.f32.bf16.bf16.f32 "
                        "{%0,%1,%2,%3}, {%4,%5,%6,%7}, {%8,%9}, {%0,%1,%2,%3};\n"
                        : "+f"(acc[mi][ni][0]), "+f"(acc[mi][ni][1]),
                          "+f"(acc[mi][ni][2]), "+f"(acc[mi][ni][3])
                        : "r"(a[mi][0]), "r"(a[mi][1]), "r"(a[mi][2]), "r"(a[mi][3]),
                          "r"(b0), "r"(b1));
                }
        }
    };

    // ---- pipeline: double buffer, register prefetch distance 1 ----
    gload(nb0);
    sstore(0);
    __syncthreads();

#pragma unroll 1
    for (int it = 0; it < ITERS; ++it) {
        const int buf = it & 1;
        if (it + 1 < ITERS) gload(nb0 + (it + 1) * BK);
        compute(buf);
        if (it + 1 < ITERS) sstore(buf ^ 1);
        __syncthreads();
    }

    // ---- epilogue: packed float2 L2 atomics into partial G[m][d] ----
#pragma unroll
    for (int mi = 0; mi < 2; mi++)
#pragma unroll
        for (int ni = 0; ni < 4; ni++) {
            int m = wm + mi * 16 + g;
            int n = d0 + wn + ni * 8 + 2 * t;
            atomicAdd((float2*)&g_partial[m * DDIM + n],
                      make_float2(acc[mi][ni][0], acc[mi][ni][1]));
            atomicAdd((float2*)&g_partial[(m + 8) * DDIM + n],
                      make_float2(acc[mi][ni][2], acc[mi][ni][3]));
        }

    // ---- h2 block reduce, one atomic per CTA ----
#pragma unroll
    for (int o = 16; o > 0; o >>= 1) h2 += __shfl_xor_sync(0xffffffffu, h2, o);
    if (lane == 0) redbuf[wid] = h2;
    __syncthreads();
    if (tid == 0) {
        float s = 0.f;
#pragma unroll
        for (int w = 0; w < 8; w++) s += redbuf[w];
        atomicAdd(&g_h2sum, s);
    }

    // ---- last-CTA finalize: square-sum G, write scalar, reset state ----
    __threadfence();
    if (tid == 0) s_ticket = atomicAdd(&g_count, 1u);
    __syncthreads();
    if (s_ticket != NCTAS - 1) return;

    double s = 0.0;
    for (int i = tid; i < KCL * DDIM; i += 256) {
        float v = __ldcg(&g_partial[i]);
        s += (double)v * (double)v;
        g_partial[i] = 0.f;              // re-zero for next graph replay
    }
#pragma unroll
    for (int o = 16; o > 0; o >>= 1) s += __shfl_xor_sync(0xffffffffu, s, o);
    if (lane == 0) sb[wid] = s;
    __syncthreads();
    if (tid == 0) {
        double tot = 0.0;
#pragma unroll
        for (int w = 0; w < 8; w++) tot += sb[w];
        float h2tot = __ldcg(&g_h2sum);
        out[0] = (float)((double)h2tot - tot);
        g_h2sum = 0.f;
        g_count = 0u;
    }
}

extern "C" void kernel_launch(void* const* d_in, const int* in_sizes, int n_in,
                              void* d_out, int out_size) {
    const float* Hp;
    const float* Fp;
    if (in_sizes[0] == NTOT * DDIM) {
        Hp = (const float*)d_in[0];
        Fp = (const float*)d_in[1];
    } else {
        Hp = (const float*)d_in[1];
        Fp = (const float*)d_in[0];
    }

    dim3 grid(DTILES, NCHUNKS);
    k_fused<<<grid, 256>>>(Hp, Fp, (float*)d_out);
}

// round 14
// speedup vs baseline: 1.4640x; 1.1338x over previous
#include <cuda_runtime.h>
#include <cuda_bf16.h>
#include <cstdint>

#define NTOT 65536
#define DDIM 512
#define KCL  64

#define BN 64               // d-columns per CTA tile (halved for occupancy)
#define BK 32               // k rows per stage
#define DTILES 8            // DDIM / BN
#define NCHUNKS 74          // grid = 8*74 = 592 CTAs = 4 CTAs/SM, one wave
#define NCTAS (DTILES * NCHUNKS)

#define SF_B 144            // F smem row stride bytes (64 bf16 = 128 + 16 pad)
#define SH_B 144            // H smem row stride bytes (64 bf16 = 128 + 16 pad)

__device__ float        g_partial[KCL * DDIM];  // .bss zero; re-zeroed per call
__device__ float        g_h2sum;
__device__ unsigned int g_count;

__device__ __forceinline__ uint32_t smem_u32(const void* p) {
    return (uint32_t)__cvta_generic_to_shared(p);
}

__device__ __forceinline__ uint32_t pack_bf16(float lo, float hi) {
    uint32_t r;
    asm("cvt.rn.bf16x2.f32 %0, %1, %2;" : "=r"(r) : "f"(hi), "f"(lo));
    return r;
}

__device__ __forceinline__ void ldsm4t(uint32_t* r, uint32_t addr) {
    asm volatile(
        "ldmatrix.sync.aligned.m8n8.x4.trans.shared.b16 {%0,%1,%2,%3}, [%4];"
        : "=r"(r[0]), "=r"(r[1]), "=r"(r[2]), "=r"(r[3]) : "r"(addr));
}

__global__ __launch_bounds__(256, 4)
void k_fused(const float* __restrict__ H, const float* __restrict__ Fm,
             float* __restrict__ out) {
    // smem tiles in gmem order: rows = k
    __shared__ __align__(16) char Fs[2][BK * SF_B];   // 2 x 4608 B
    __shared__ __align__(16) char Hs[2][BK * SH_B];   // 2 x 4608 B
    __shared__ float        redbuf[8];
    __shared__ double       sb[8];
    __shared__ unsigned int s_ticket;

    const int tid  = threadIdx.x;
    const int lane = tid & 31;
    const int wid  = tid >> 5;
    const int d0   = blockIdx.x * BN;
    const int c    = blockIdx.y;

    // 2048 k-blocks over 74 chunks: chunks 0..49 get 28, 50..73 get 27
    const int kb_start = c * 27 + (c < 50 ? c : 50);
    const int ITERS    = 27 + (c < 50 ? 1 : 0);
    const int nb0      = kb_start * BK;

    const int wm = (wid >> 1) * 16;     // 4 warp rows along m (16 each)
    const int wn = (wid & 1) * 32;      // 2 warp cols along n (32 each)
    const int g  = lane >> 2;
    const int t  = lane & 3;

    // producer mapping: thread -> rows (tid>>4) and (tid>>4)+16, quad tid&15
    const int pr = tid >> 4;            // 0..15
    const int pq = tid & 15;            // float4 index within row

    // LDSM per-lane offsets (bytes) — R9-proven formulas
    const uint32_t a_lane = (uint32_t)(((lane >> 4) & 1) * (8 * SF_B)
                                       + (lane & 7) * SF_B
                                       + ((lane >> 3) & 1) * 16);
    const uint32_t b_lane = (uint32_t)(((lane >> 3) & 1) * (8 * SH_B)
                                       + (lane & 7) * SH_B
                                       + ((lane >> 4) & 1) * 16);

    float acc[4][4];                    // [ni][frag] — warp tile m16 x n32
#pragma unroll
    for (int a = 0; a < 4; a++)
#pragma unroll
        for (int b = 0; b < 4; b++) acc[a][b] = 0.f;

    float h2 = 0.f;

    float4 rf[2], rh[2];

    auto gload = [&](int nb) {
#pragma unroll
        for (int j = 0; j < 2; j++) {
            const int k = nb + pr + 16 * j;
            rf[j] = *(const float4*)&Fm[(size_t)k * KCL + pq * 4];
            rh[j] = *(const float4*)&H[(size_t)k * DDIM + d0 + pq * 4];
        }
    };

    auto sstore = [&](int buf) {
        char* fb = Fs[buf];
        char* hb = Hs[buf];
#pragma unroll
        for (int j = 0; j < 2; j++) {
            const int k = pr + 16 * j;
            *(uint2*)(fb + k * SF_B + pq * 8) =
                make_uint2(pack_bf16(rf[j].x, rf[j].y),
                           pack_bf16(rf[j].z, rf[j].w));
            float4 v = rh[j];
            *(uint2*)(hb + k * SH_B + pq * 8) =
                make_uint2(pack_bf16(v.x, v.y), pack_bf16(v.z, v.w));
            h2 = fmaf(v.x, v.x, h2);
            h2 = fmaf(v.y, v.y, h2);
            h2 = fmaf(v.z, v.z, h2);
            h2 = fmaf(v.w, v.w, h2);
        }
    };

    auto compute = [&](int buf) {
        const uint32_t aBase = smem_u32(Fs[buf]) + (uint32_t)(wm * 2) + a_lane;
        const uint32_t bBase = smem_u32(Hs[buf]) + (uint32_t)(wn * 2) + b_lane;
#pragma unroll
        for (int ks = 0; ks < 2; ks++) {          // two k16 steps per BK=32
            uint32_t a[4], b[2][4];
            ldsm4t(a, aBase + ks * (16 * SF_B));
            ldsm4t(b[0], bBase + ks * (16 * SH_B));
            ldsm4t(b[1], bBase + ks * (16 * SH_B) + 32);      // n + 16
#pragma unroll
            for (int ni = 0; ni < 4; ni++) {
                const uint32_t b0 = b[ni >> 1][(ni & 1) * 2];
                const uint32_t b1 = b[ni >> 1][(ni & 1) * 2 + 1];
                asm volatile(
                    "mma.sync.aligned.m16n8k16.row.col.f32.bf16.bf16.f32 "
                    "{%0,%1,%2,%3}, {%4,%5,%6,%7}, {%8,%9}, {%0,%1,%2,%3};\n"
                    : "+f"(acc[ni][0]), "+f"(acc[ni][1]),
                      "+f"(acc[ni][2]), "+f"(acc[ni][3])
                    : "r"(a[0]), "r"(a[1]), "r"(a[2]), "r"(a[3]),
                      "r"(b0), "r"(b1));
            }
        }
    };

    // ---- pipeline: double buffer, register prefetch distance 1 ----
    gload(nb0);
    sstore(0);
    __syncthreads();

#pragma unroll 1
    for (int it = 0; it < ITERS; ++it) {
        const int buf = it & 1;
        if (it + 1 < ITERS) gload(nb0 + (it + 1) * BK);
        compute(buf);
        if (it + 1 < ITERS) sstore(buf ^ 1);
        __syncthreads();
    }

    // ---- epilogue: packed float2 L2 atomics into partial G[m][d] ----
#pragma unroll
    for (int ni = 0; ni < 4; ni++) {
        int m = wm + g;
        int n = d0 + wn + ni * 8 + 2 * t;
        atomicAdd((float2*)&g_partial[m * DDIM + n],
                  make_float2(acc[ni][0], acc[ni][1]));
        atomicAdd((float2*)&g_partial[(m + 8) * DDIM + n],
                  make_float2(acc[ni][2], acc[ni][3]));
    }

    // ---- h2 block reduce, one atomic per CTA ----
#pragma unroll
    for (int o = 16; o > 0; o >>= 1) h2 += __shfl_xor_sync(0xffffffffu, h2, o);
    if (lane == 0) redbuf[wid] = h2;
    __syncthreads();
    if (tid == 0) {
        float s = 0.f;
#pragma unroll
        for (int w = 0; w < 8; w++) s += redbuf[w];
        atomicAdd(&g_h2sum, s);
    }

    // ---- last-CTA finalize: square-sum G, write scalar, reset state ----
    __threadfence();
    if (tid == 0) s_ticket = atomicAdd(&g_count, 1u);
    __syncthreads();
    if (s_ticket != NCTAS - 1) return;

    double s = 0.0;
    for (int i = tid; i < KCL * DDIM; i += 256) {
        float v = __ldcg(&g_partial[i]);
        s += (double)v * (double)v;
        g_partial[i] = 0.f;              // re-zero for next graph replay
    }
#pragma unroll
    for (int o = 16; o > 0; o >>= 1) s += __shfl_xor_sync(0xffffffffu, s, o);
    if (lane == 0) sb[wid] = s;
    __syncthreads();
    if (tid == 0) {
        double tot = 0.0;
#pragma unroll
        for (int w = 0; w < 8; w++) tot += sb[w];
        float h2tot = __ldcg(&g_h2sum);
        out[0] = (float)((double)h2tot - tot);
        g_h2sum = 0.f;
        g_count = 0u;
    }
}

extern "C" void kernel_launch(void* const* d_in, const int* in_sizes, int n_in,
                              void* d_out, int out_size) {
    const float* Hp;
    const float* Fp;
    if (in_sizes[0] == NTOT * DDIM) {
        Hp = (const float*)d_in[0];
        Fp = (const float*)d_in[1];
    } else {
        Hp = (const float*)d_in[1];
        Fp = (const float*)d_in[0];
    }

    dim3 grid(DTILES, NCHUNKS);
    k_fused<<<grid, 256>>>(Hp, Fp, (float*)d_out);
}

// round 15
// speedup vs baseline: 1.4681x; 1.0028x over previous
#include <cuda_runtime.h>
#include <cuda_bf16.h>
#include <cuda_fp16.h>
#include <cstdint>

#define NTOT 65536
#define DDIM 512
#define KCL  64

#define BN 64               // d-columns per CTA tile
#define BK 32               // k rows per stage
#define DTILES 8            // DDIM / BN
#define NCHUNKS 74          // grid = 8*74 = 592 CTAs = 4 CTAs/SM, one wave
#define NCTAS (DTILES * NCHUNKS)

#define SF_B 144            // F smem row stride bytes (64 f16 = 128 + 16 pad)
#define SH_B 144            // H smem row stride bytes (64 f16 = 128 + 16 pad)

__device__ float        g_partial[KCL * DDIM];  // .bss zero; re-zeroed per call
__device__ float        g_h2sum;
__device__ unsigned int g_count;

__device__ __forceinline__ uint32_t smem_u32(const void* p) {
    return (uint32_t)__cvta_generic_to_shared(p);
}

__device__ __forceinline__ uint32_t pack_f16(float lo, float hi) {
    uint32_t r;
    asm("cvt.rn.f16x2.f32 %0, %1, %2;" : "=r"(r) : "f"(hi), "f"(lo));
    return r;
}

__device__ __forceinline__ void ldsm4t(uint32_t* r, uint32_t addr) {
    asm volatile(
        "ldmatrix.sync.aligned.m8n8.x4.trans.shared.b16 {%0,%1,%2,%3}, [%4];"
        : "=r"(r[0]), "=r"(r[1]), "=r"(r[2]), "=r"(r[3]) : "r"(addr));
}

__global__ __launch_bounds__(256, 4)
void k_fused(const float* __restrict__ H, const float* __restrict__ Fm,
             float* __restrict__ out) {
    // smem tiles in gmem order: rows = k
    __shared__ __align__(16) char Fs[2][BK * SF_B];   // 2 x 4608 B
    __shared__ __align__(16) char Hs[2][BK * SH_B];   // 2 x 4608 B
    __shared__ float        redbuf[8];
    __shared__ double       sb[8];
    __shared__ unsigned int s_ticket;

    const int tid  = threadIdx.x;
    const int lane = tid & 31;
    const int wid  = tid >> 5;
    const int d0   = blockIdx.x * BN;
    const int c    = blockIdx.y;

    // 2048 k-blocks over 74 chunks: chunks 0..49 get 28, 50..73 get 27
    const int kb_start = c * 27 + (c < 50 ? c : 50);
    const int ITERS    = 27 + (c < 50 ? 1 : 0);
    const int nb0      = kb_start * BK;

    const int wm = (wid >> 1) * 16;     // 4 warp rows along m (16 each)
    const int wn = (wid & 1) * 32;      // 2 warp cols along n (32 each)
    const int g  = lane >> 2;
    const int t  = lane & 3;

    // producer mapping: thread -> rows (tid>>4) and (tid>>4)+16, quad tid&15
    const int pr = tid >> 4;            // 0..15
    const int pq = tid & 15;            // float4 index within row

    // LDSM per-lane offsets (bytes) — R9-proven formulas
    const uint32_t a_lane = (uint32_t)(((lane >> 4) & 1) * (8 * SF_B)
                                       + (lane & 7) * SF_B
                                       + ((lane >> 3) & 1) * 16);
    const uint32_t b_lane = (uint32_t)(((lane >> 3) & 1) * (8 * SH_B)
                                       + (lane & 7) * SH_B
                                       + ((lane >> 4) & 1) * 16);

    // f16 accumulators: [ni] x {c0 = (m=g, n=2t..2t+1), c1 = (m=g+8, same n)}
    uint32_t acc[4][2];
#pragma unroll
    for (int a = 0; a < 4; a++) { acc[a][0] = 0u; acc[a][1] = 0u; }

    float h2 = 0.f;

    float4 rf[2], rh[2];

    auto gload = [&](int nb) {
#pragma unroll
        for (int j = 0; j < 2; j++) {
            const int k = nb + pr + 16 * j;
            rf[j] = *(const float4*)&Fm[(size_t)k * KCL + pq * 4];
            rh[j] = *(const float4*)&H[(size_t)k * DDIM + d0 + pq * 4];
        }
    };

    auto sstore = [&](int buf) {
        char* fb = Fs[buf];
        char* hb = Hs[buf];
#pragma unroll
        for (int j = 0; j < 2; j++) {
            const int k = pr + 16 * j;
            *(uint2*)(fb + k * SF_B + pq * 8) =
                make_uint2(pack_f16(rf[j].x, rf[j].y),
                           pack_f16(rf[j].z, rf[j].w));
            float4 v = rh[j];
            *(uint2*)(hb + k * SH_B + pq * 8) =
                make_uint2(pack_f16(v.x, v.y), pack_f16(v.z, v.w));
            h2 = fmaf(v.x, v.x, h2);
            h2 = fmaf(v.y, v.y, h2);
            h2 = fmaf(v.z, v.z, h2);
            h2 = fmaf(v.w, v.w, h2);
        }
    };

    auto compute = [&](int buf) {
        const uint32_t aBase = smem_u32(Fs[buf]) + (uint32_t)(wm * 2) + a_lane;
        const uint32_t bBase = smem_u32(Hs[buf]) + (uint32_t)(wn * 2) + b_lane;
#pragma unroll
        for (int ks = 0; ks < 2; ks++) {          // two k16 steps per BK=32
            uint32_t a[4], b[2][4];
            ldsm4t(a, aBase + ks * (16 * SF_B));
            ldsm4t(b[0], bBase + ks * (16 * SH_B));
            ldsm4t(b[1], bBase + ks * (16 * SH_B) + 32);      // n + 16
#pragma unroll
            for (int ni = 0; ni < 4; ni++) {
                const uint32_t b0 = b[ni >> 1][(ni & 1) * 2];
                const uint32_t b1 = b[ni >> 1][(ni & 1) * 2 + 1];
                asm volatile(
                    "mma.sync.aligned.m16n8k16.row.col.f16.f16.f16.f16 "
                    "{%0,%1}, {%2,%3,%4,%5}, {%6,%7}, {%0,%1};\n"
                    : "+r"(acc[ni][0]), "+r"(acc[ni][1])
                    : "r"(a[0]), "r"(a[1]), "r"(a[2]), "r"(a[3]),
                      "r"(b0), "r"(b1));
            }
        }
    };

    // ---- pipeline: double buffer, register prefetch distance 1 ----
    gload(nb0);
    sstore(0);
    __syncthreads();

#pragma unroll 1
    for (int it = 0; it < ITERS; ++it) {
        const int buf = it & 1;
        if (it + 1 < ITERS) gload(nb0 + (it + 1) * BK);
        compute(buf);
        if (it + 1 < ITERS) sstore(buf ^ 1);
        __syncthreads();
    }

    // ---- epilogue: unpack f16 acc, packed float2 L2 atomics ----
#pragma unroll
    for (int ni = 0; ni < 4; ni++) {
        int m = wm + g;
        int n = d0 + wn + ni * 8 + 2 * t;
        __half2 c0 = *reinterpret_cast<__half2*>(&acc[ni][0]);
        __half2 c1 = *reinterpret_cast<__half2*>(&acc[ni][1]);
        atomicAdd((float2*)&g_partial[m * DDIM + n],
                  make_float2(__low2float(c0), __high2float(c0)));
        atomicAdd((float2*)&g_partial[(m + 8) * DDIM + n],
                  make_float2(__low2float(c1), __high2float(c1)));
    }

    // ---- h2 block reduce, one atomic per CTA ----
#pragma unroll
    for (int o = 16; o > 0; o >>= 1) h2 += __shfl_xor_sync(0xffffffffu, h2, o);
    if (lane == 0) redbuf[wid] = h2;
    __syncthreads();
    if (tid == 0) {
        float s = 0.f;
#pragma unroll
        for (int w = 0; w < 8; w++) s += redbuf[w];
        atomicAdd(&g_h2sum, s);
    }

    // ---- last-CTA finalize: square-sum G, write scalar, reset state ----
    __threadfence();
    if (tid == 0) s_ticket = atomicAdd(&g_count, 1u);
    __syncthreads();
    if (s_ticket != NCTAS - 1) return;

    double s = 0.0;
    for (int i = tid; i < KCL * DDIM; i += 256) {
        float v = __ldcg(&g_partial[i]);
        s += (double)v * (double)v;
        g_partial[i] = 0.f;              // re-zero for next graph replay
    }
#pragma unroll
    for (int o = 16; o > 0; o >>= 1) s += __shfl_xor_sync(0xffffffffu, s, o);
    if (lane == 0) sb[wid] = s;
    __syncthreads();
    if (tid == 0) {
        double tot = 0.0;
#pragma unroll
        for (int w = 0; w < 8; w++) tot += sb[w];
        float h2tot = __ldcg(&g_h2sum);
        out[0] = (float)((double)h2tot - tot);
        g_h2sum = 0.f;
        g_count = 0u;
    }
}

extern "C" void kernel_launch(void* const* d_in, const int* in_sizes, int n_in,
                              void* d_out, int out_size) {
    const float* Hp;
    const float* Fp;
    if (in_sizes[0] == NTOT * DDIM) {
        Hp = (const float*)d_in[0];
        Fp = (const float*)d_in[1];
    } else {
        Hp = (const float*)d_in[1];
        Fp = (const float*)d_in[0];
    }

    dim3 grid(DTILES, NCHUNKS);
    k_fused<<<grid, 256>>>(Hp, Fp, (float*)d_out);
}